// round 15
// baseline (speedup 1.0000x reference)
#include <cuda_runtime.h>
#include <cstdint>

#define N_NODES 100000
#define E_EDGES 1600000
#define F       128
#define C_OUT   64
#define NB      592          // persistent grid: 4 blocks/SM on 148 SMs

// ---- device scratch ----
__device__ int   g_cnt[N_NODES];                 // in-degree histogram (excl. self)
__device__ int   g_ptr[N_NODES + 1];             // CSR row pointers (by target)
__device__ int   g_pos[N_NODES];                 // fill cursors
__device__ int   g_bsum[256];
__device__ int   g_boff[256];
__device__ int   g_csr[E_EDGES];                 // source node per CSR slot
__device__ float g_dinv[N_NODES];
__device__ float g_wcomb[F * C_OUT];             // W_gcn @ W_fc^T
__device__ float g_xws[(size_t)N_NODES * C_OUT]; // dinv * (x @ Wcomb)
__device__ float g_bfc2[C_OUT];                  // b_fc + W_fc @ b_gcn
__device__ unsigned g_arrive;                    // grid barrier counter (reset by k_gather)

// ---- grid-wide spin barrier (all NB blocks must call) ----
__device__ __forceinline__ void gbar(unsigned target) {
    __syncthreads();
    if (threadIdx.x == 0) {
        __threadfence();
        atomicAdd(&g_arrive, 1u);
        while (*((volatile unsigned*)&g_arrive) < target) { }
        __threadfence();
    }
    __syncthreads();
}

// ==================== persistent CSR builder ====================
// Phase A: wcomb + bfc2 + zero cnt
// Phase B: histogram over targets
// Phase C: 3-step exclusive scan (+ pos, dinv)
// Phase D: CSR fill
__global__ void __launch_bounds__(256, 4)
k_mega(const float* __restrict__ Wg, const float* __restrict__ Wfc,
       const float* __restrict__ bgcn, const float* __restrict__ bfc,
       const int* __restrict__ ei, int n, int e, int nbs) {
    int b = blockIdx.x;
    int t = threadIdx.x;
    int lane = t & 31;
    int w = t >> 5;

    // ---------- Phase A ----------
    // wcomb[k][c] = sum_j Wg[k][j]*Wfc[c][j]; one warp per output, grid-strided
    for (int idx = b * 8 + w; idx < F * C_OUT; idx += NB * 8) {
        int k = idx >> 6, c = idx & 63;
        const float* wg = Wg + k * F;
        const float* wf = Wfc + c * F;
        float s = wg[lane] * wf[lane];
        s = fmaf(wg[lane + 32], wf[lane + 32], s);
        s = fmaf(wg[lane + 64], wf[lane + 64], s);
        s = fmaf(wg[lane + 96], wf[lane + 96], s);
#pragma unroll
        for (int o = 16; o > 0; o >>= 1) s += __shfl_xor_sync(0xffffffffu, s, o);
        if (lane == 0) g_wcomb[idx] = s;
    }
    if (b == 0) {   // bfc2: 8 warps x 8 outputs
#pragma unroll
        for (int cc = 0; cc < 8; ++cc) {
            int c = w * 8 + cc;
            const float* wf = Wfc + c * F;
            float s = bgcn[lane] * wf[lane];
            s = fmaf(bgcn[lane + 32], wf[lane + 32], s);
            s = fmaf(bgcn[lane + 64], wf[lane + 64], s);
            s = fmaf(bgcn[lane + 96], wf[lane + 96], s);
#pragma unroll
            for (int o = 16; o > 0; o >>= 1) s += __shfl_xor_sync(0xffffffffu, s, o);
            if (lane == 0) g_bfc2[c] = s + bfc[c];
        }
    }
    // zero g_cnt
    for (int i4 = b * 256 + t; i4 * 4 < n; i4 += NB * 256) {
        int base = i4 * 4;
        if (base + 3 < n) *(int4*)&g_cnt[base] = make_int4(0, 0, 0, 0);
        else for (int j = base; j < n; ++j) g_cnt[j] = 0;
    }

    gbar(NB * 1u);

    // ---------- Phase B: histogram ----------
    {
        const int* col = ei + e;
        for (int i4 = b * 256 + t; i4 * 4 < e; i4 += NB * 256) {
            int base = i4 * 4;
            if (base + 3 < e) {
                int4 c = *(const int4*)&col[base];
                atomicAdd(&g_cnt[c.x], 1);
                atomicAdd(&g_cnt[c.y], 1);
                atomicAdd(&g_cnt[c.z], 1);
                atomicAdd(&g_cnt[c.w], 1);
            } else {
                for (int j = base; j < e; ++j) atomicAdd(&g_cnt[col[j]], 1);
            }
        }
    }

    gbar(NB * 2u);

    // ---------- Phase C1: per-chunk local scan ----------
    {
        __shared__ int wsh[8];
        __shared__ int woff[8];
        if (b < nbs) {
            int base = b * 1024 + t * 4;
            int x0 = 0, x1 = 0, x2 = 0, x3 = 0;
            if (base + 3 < n) {
                int4 v = *(const int4*)&g_cnt[base];
                x0 = v.x; x1 = v.y; x2 = v.z; x3 = v.w;
            } else if (base < n) {
                x0 = g_cnt[base];
                if (base + 1 < n) x1 = g_cnt[base + 1];
                if (base + 2 < n) x2 = g_cnt[base + 2];
            }
            int s0 = x0, s1 = s0 + x1, s2 = s1 + x2, s3 = s2 + x3;
            int ws = s3;
#pragma unroll
            for (int o = 1; o < 32; o <<= 1) {
                int u = __shfl_up_sync(0xffffffffu, ws, o);
                if (lane >= o) ws += u;
            }
            if (lane == 31) wsh[w] = ws;
            __syncthreads();
            if (t == 0) {
                int acc = 0;
#pragma unroll
                for (int i = 0; i < 8; ++i) { woff[i] = acc; acc += wsh[i]; }
                g_bsum[b] = acc;
            }
            __syncthreads();
            int excl = woff[w] + ws - s3;
            if (base < n)     g_ptr[base]     = excl;
            if (base + 1 < n) g_ptr[base + 1] = excl + s0;
            if (base + 2 < n) g_ptr[base + 2] = excl + s1;
            if (base + 3 < n) g_ptr[base + 3] = excl + s2;
        }
    }

    gbar(NB * 3u);

    // ---------- Phase C2: scan of block sums (block 0) ----------
    {
        __shared__ int wsh2[8];
        __shared__ int woff2[8];
        if (b == 0) {
            int v = (t < nbs) ? g_bsum[t] : 0;
            int ws = v;
#pragma unroll
            for (int o = 1; o < 32; o <<= 1) {
                int u = __shfl_up_sync(0xffffffffu, ws, o);
                if (lane >= o) ws += u;
            }
            if (lane == 31) wsh2[w] = ws;
            __syncthreads();
            if (t == 0) {
                int acc = 0;
#pragma unroll
                for (int i = 0; i < 8; ++i) { woff2[i] = acc; acc += wsh2[i]; }
            }
            __syncthreads();
            if (t < nbs) g_boff[t] = woff2[w] + ws - v;
        }
    }

    gbar(NB * 4u);

    // ---------- Phase C3: add offsets; write ptr/pos/dinv ----------
    if (b < nbs) {
        int off = g_boff[b];
        int base = b * 1024 + t * 4;
#pragma unroll
        for (int j = 0; j < 4; ++j) {
            int i = base + j;
            if (i < n) {
                int p = g_ptr[i] + off;
                g_ptr[i] = p;
                g_pos[i] = p;
                g_dinv[i] = rsqrtf((float)(g_cnt[i] + 1));
            }
        }
        if (b == 0 && t == 0) g_ptr[n] = e;
    }

    gbar(NB * 5u);

    // ---------- Phase D: CSR fill ----------
    for (int u = b * 256 + t; u * 2 < e; u += NB * 256) {
        int i = u * 2;
        int2 rows = *(const int2*)&ei[i];
        int2 cols = *(const int2*)&ei[e + i];
        int p0 = atomicAdd(&g_pos[cols.x], 1);
        g_csr[p0] = rows.x;
        if (i + 1 < e) {
            int p1 = atomicAdd(&g_pos[cols.y], 1);
            g_csr[p1] = rows.y;
        }
    }
}

// ==================== GEMM: xws = dinv * (x @ Wcomb) ====================
// tile: 128 rows x 64 cols, 256 threads, each thread 8 rows x 4 cols (unchanged from R12)
__global__ void k_xw(const float* __restrict__ x, int n) {
    extern __shared__ float sh[];
    float* Wsm = sh;               // 128*64 = 32 KB  [k][c]
    float* Xsm = sh + F * C_OUT;   // 128*128 = 64 KB [r][k]

    int t = threadIdx.x;
    for (int i = t; i < (F * C_OUT) / 4; i += 256)
        ((float4*)Wsm)[i] = ((const float4*)g_wcomb)[i];

    int base = blockIdx.x * 128;
    for (int i = t; i < 128 * 32; i += 256) {
        int rr = i >> 5, cc = i & 31;
        int r = base + rr;
        float4 v = make_float4(0.f, 0.f, 0.f, 0.f);
        if (r < n) v = ((const float4*)x)[(size_t)r * 32 + cc];
        ((float4*)Xsm)[i] = v;
    }
    __syncthreads();

    int tx = t & 15;
    int ty = t >> 4;
    int c0 = tx * 4, r0 = ty * 8;

    float acc[8][4];
#pragma unroll
    for (int i = 0; i < 8; ++i)
#pragma unroll
        for (int j = 0; j < 4; ++j) acc[i][j] = 0.f;

#pragma unroll 4
    for (int k = 0; k < F; ++k) {
        float4 w = *(const float4*)&Wsm[k * C_OUT + c0];
#pragma unroll
        for (int i = 0; i < 8; ++i) {
            float xv = Xsm[(r0 + i) * F + k];
            acc[i][0] = fmaf(xv, w.x, acc[i][0]);
            acc[i][1] = fmaf(xv, w.y, acc[i][1]);
            acc[i][2] = fmaf(xv, w.z, acc[i][2]);
            acc[i][3] = fmaf(xv, w.w, acc[i][3]);
        }
    }

#pragma unroll
    for (int i = 0; i < 8; ++i) {
        int r = base + r0 + i;
        if (r < n) {
            float dv = g_dinv[r];
            float4 v;
            v.x = dv * acc[i][0];
            v.y = dv * acc[i][1];
            v.z = dv * acc[i][2];
            v.w = dv * acc[i][3];
            *(float4*)&g_xws[(size_t)r * C_OUT + c0] = v;
        }
    }
}

// ==================== gather + epilogue (unchanged from R12) ====================
// 16 threads per node, each owns one float4 column slot
__global__ void k_gather(float* __restrict__ out, int n) {
    if (blockIdx.x == 0 && threadIdx.x == 0) g_arrive = 0;  // reset for next replay

    int gt = blockIdx.x * blockDim.x + threadIdx.x;
    int r = gt >> 4;
    if (r >= n) return;
    int l4 = (gt & 15) * 4;

    int p0 = __ldg(&g_ptr[r]);
    int p1 = __ldg(&g_ptr[r + 1]);

    float4 acc = *(const float4*)&g_xws[(size_t)r * C_OUT + l4];  // self-loop

    int j = p0;
    int nxt = (j < p1) ? __ldg(&g_csr[j]) : 0;
    while (j < p1) {
        int idx = nxt;
        ++j;
        nxt = (j < p1) ? __ldg(&g_csr[j]) : 0;
        float4 v = *(const float4*)&g_xws[(size_t)idx * C_OUT + l4];
        acc.x += v.x; acc.y += v.y; acc.z += v.z; acc.w += v.w;
    }

    float dv = __ldg(&g_dinv[r]);
    float4 b = *(const float4*)&g_bfc2[l4];
    float4 o;
    o.x = fmaf(dv, acc.x, b.x);
    o.y = fmaf(dv, acc.y, b.y);
    o.z = fmaf(dv, acc.z, b.z);
    o.w = fmaf(dv, acc.w, b.w);
    *(float4*)&out[(size_t)r * C_OUT + l4] = o;
}

// ==================== launch: 3 kernels ====================
extern "C" void kernel_launch(void* const* d_in, const int* in_sizes, int n_in,
                              void* d_out, int out_size) {
    const float* x    = (const float*)d_in[0];
    const int*   ei   = (const int*)d_in[1];
    const float* Wgcn = (const float*)d_in[2];
    const float* bgcn = (const float*)d_in[3];
    const float* Wfc  = (const float*)d_in[4];
    const float* bfc  = (const float*)d_in[5];
    float* out = (float*)d_out;

    int n = in_sizes[0] / F;       // 100000
    int e = in_sizes[1] / 2;       // 1600000

    static bool attr_set = false;
    if (!attr_set) {
        cudaFuncSetAttribute(k_xw, cudaFuncAttributeMaxDynamicSharedMemorySize,
                             (F * C_OUT + 128 * F) * 4);
        attr_set = true;
    }

    int nbs = (n + 1023) / 1024;   // 98 (<=128, <=NB)

    k_mega<<<NB, 256>>>(Wgcn, Wfc, bgcn, bfc, ei, n, e, nbs);

    int gemm_blocks = (n + 127) / 128;
    k_xw<<<gemm_blocks, 256, (F * C_OUT + 128 * F) * 4>>>(x, n);

    k_gather<<<(n * 16 + 255) / 256, 256>>>(out, n);
}

// round 16
// speedup vs baseline: 1.1682x; 1.1682x over previous
#include <cuda_runtime.h>
#include <cstdint>

#define N_NODES 100000
#define E_EDGES 1600000
#define F       128
#define C_OUT   64

typedef unsigned long long u64;

// ---- device scratch ----
__device__ int   g_cnt[N_NODES];                 // in-degree histogram (excl. self)
__device__ int   g_ptr[N_NODES + 1];             // CSR row pointers (by target)
__device__ int   g_pos[N_NODES];                 // fill cursors
__device__ int   g_bsum[256];
__device__ int   g_boff[256];
__device__ int   g_csr[E_EDGES];                 // source node per CSR slot
__device__ float g_dinv[N_NODES];
__device__ float g_wcomb[F * C_OUT];             // W_gcn @ W_fc^T
__device__ float g_xws[(size_t)N_NODES * C_OUT]; // dinv * (x @ Wcomb)
__device__ float g_bfc2[C_OUT];                  // b_fc + W_fc @ b_gcn

// ==================== fused setup: wcomb + bfc2 + zero cnt ====================
__global__ void k_setup(const float* __restrict__ Wg, const float* __restrict__ Wfc,
                        const float* __restrict__ bgcn, const float* __restrict__ bfc,
                        int n) {
    int b = blockIdx.x;
    int t = threadIdx.x;
    int lane = t & 31;
    int w = t >> 5;
    if (b < 1024) {
        int idx = b * 8 + w;                  // 0..8191
        int k = idx >> 6, c = idx & 63;
        const float* wg = Wg + k * F;
        const float* wf = Wfc + c * F;
        float s = wg[lane] * wf[lane];
        s = fmaf(wg[lane + 32], wf[lane + 32], s);
        s = fmaf(wg[lane + 64], wf[lane + 64], s);
        s = fmaf(wg[lane + 96], wf[lane + 96], s);
#pragma unroll
        for (int o = 16; o > 0; o >>= 1) s += __shfl_xor_sync(0xffffffffu, s, o);
        if (lane == 0) g_wcomb[idx] = s;
        return;
    }
    if (b == 1024) {
#pragma unroll
        for (int cc = 0; cc < 8; ++cc) {
            int c = w * 8 + cc;
            const float* wf = Wfc + c * F;
            float s = bgcn[lane] * wf[lane];
            s = fmaf(bgcn[lane + 32], wf[lane + 32], s);
            s = fmaf(bgcn[lane + 64], wf[lane + 64], s);
            s = fmaf(bgcn[lane + 96], wf[lane + 96], s);
#pragma unroll
            for (int o = 16; o > 0; o >>= 1) s += __shfl_xor_sync(0xffffffffu, s, o);
            if (lane == 0) g_bfc2[c] = s + bfc[c];
        }
        return;
    }
    // zero g_cnt: 1024 ints per block
    int base = (b - 1025) * 1024 + t * 4;
    if (base + 3 < n) *(int4*)&g_cnt[base] = make_int4(0, 0, 0, 0);
    else for (int j = base; j < n; ++j) g_cnt[j] = 0;
}

// ==================== histogram over targets ====================
__global__ void k_hist(const int* __restrict__ col, int e) {
    int base = (blockIdx.x * blockDim.x + threadIdx.x) * 4;
    if (base >= e) return;
    if (base + 3 < e) {
        int4 c = *(const int4*)&col[base];
        atomicAdd(&g_cnt[c.x], 1);
        atomicAdd(&g_cnt[c.y], 1);
        atomicAdd(&g_cnt[c.z], 1);
        atomicAdd(&g_cnt[c.w], 1);
    } else {
        for (int j = base; j < e; ++j) atomicAdd(&g_cnt[col[j]], 1);
    }
}

// ==================== exclusive scan (3 kernels) ====================
__global__ void k_scan1(int n) {
    __shared__ int wsh[8];
    __shared__ int woff[8];
    int t = threadIdx.x, b = blockIdx.x;
    int base = b * 1024 + t * 4;
    int x0 = 0, x1 = 0, x2 = 0, x3 = 0;
    if (base + 3 < n) {
        int4 v = *(const int4*)&g_cnt[base];
        x0 = v.x; x1 = v.y; x2 = v.z; x3 = v.w;
    } else if (base < n) {
        x0 = g_cnt[base];
        if (base + 1 < n) x1 = g_cnt[base + 1];
        if (base + 2 < n) x2 = g_cnt[base + 2];
    }
    int s0 = x0, s1 = s0 + x1, s2 = s1 + x2, s3 = s2 + x3;
    int lane = t & 31, w = t >> 5;
    int ws = s3;
#pragma unroll
    for (int o = 1; o < 32; o <<= 1) {
        int u = __shfl_up_sync(0xffffffffu, ws, o);
        if (lane >= o) ws += u;
    }
    if (lane == 31) wsh[w] = ws;
    __syncthreads();
    if (t == 0) {
        int acc = 0;
#pragma unroll
        for (int i = 0; i < 8; ++i) { woff[i] = acc; acc += wsh[i]; }
        g_bsum[b] = acc;
    }
    __syncthreads();
    int excl = woff[w] + ws - s3;
    if (base < n)     g_ptr[base]     = excl;
    if (base + 1 < n) g_ptr[base + 1] = excl + s0;
    if (base + 2 < n) g_ptr[base + 2] = excl + s1;
    if (base + 3 < n) g_ptr[base + 3] = excl + s2;
}

__global__ void k_scan2(int nb) {
    __shared__ int wsh[8];
    __shared__ int woff[8];
    int t = threadIdx.x;
    int v = (t < nb) ? g_bsum[t] : 0;
    int lane = t & 31, w = t >> 5;
    int ws = v;
#pragma unroll
    for (int o = 1; o < 32; o <<= 1) {
        int u = __shfl_up_sync(0xffffffffu, ws, o);
        if (lane >= o) ws += u;
    }
    if (lane == 31) wsh[w] = ws;
    __syncthreads();
    if (t == 0) {
        int acc = 0;
#pragma unroll
        for (int i = 0; i < 8; ++i) { woff[i] = acc; acc += wsh[i]; }
    }
    __syncthreads();
    if (t < nb) g_boff[t] = woff[w] + ws - v;
}

__global__ void k_scan3(int n, int e) {
    int t = threadIdx.x, b = blockIdx.x;
    int off = g_boff[b];
    int base = b * 1024 + t * 4;
#pragma unroll
    for (int j = 0; j < 4; ++j) {
        int i = base + j;
        if (i < n) {
            int p = g_ptr[i] + off;
            g_ptr[i] = p;
            g_pos[i] = p;
            g_dinv[i] = rsqrtf((float)(g_cnt[i] + 1));
        }
    }
    if (b == 0 && t == 0) g_ptr[n] = e;
}

// ==================== CSR fill: bucket source rows by target ====================
__global__ void k_fill(const int* __restrict__ ei, int e) {
    int i = (blockIdx.x * blockDim.x + threadIdx.x) * 2;
    if (i >= e) return;
    int2 rows = *(const int2*)&ei[i];       // i even -> 8B aligned
    int2 cols = *(const int2*)&ei[e + i];   // e even -> 8B aligned
    int p0 = atomicAdd(&g_pos[cols.x], 1);
    g_csr[p0] = rows.x;
    if (i + 1 < e) {
        int p1 = atomicAdd(&g_pos[cols.y], 1);
        g_csr[p1] = rows.y;
    }
}

// ==================== GEMM: xws = dinv * (x @ Wcomb), packed f32x2 ====================
// tile: 128 rows x 64 cols, 256 threads, each thread 8 rows x 4 cols (2 packed pairs)
__global__ void k_xw(const float* __restrict__ x, int n) {
    extern __shared__ float sh[];
    float* Wsm = sh;               // 128*64 = 32 KB  [k][c]
    float* Xsm = sh + F * C_OUT;   // 128*128 = 64 KB [r][k]

    int t = threadIdx.x;
    for (int i = t; i < (F * C_OUT) / 4; i += 256)
        ((float4*)Wsm)[i] = ((const float4*)g_wcomb)[i];

    int base = blockIdx.x * 128;
    for (int i = t; i < 128 * 32; i += 256) {
        int rr = i >> 5, cc = i & 31;
        int r = base + rr;
        float4 v = make_float4(0.f, 0.f, 0.f, 0.f);
        if (r < n) v = ((const float4*)x)[(size_t)r * 32 + cc];
        ((float4*)Xsm)[i] = v;
    }
    __syncthreads();

    int tx = t & 15;
    int ty = t >> 4;
    int c0 = tx * 4, r0 = ty * 8;

    u64 acc01[8], acc23[8];       // packed {c0,c0+1} and {c0+2,c0+3} per row
#pragma unroll
    for (int i = 0; i < 8; ++i) { acc01[i] = 0ull; acc23[i] = 0ull; }

#pragma unroll 4
    for (int k = 0; k < F; ++k) {
        ulonglong2 wp = *(const ulonglong2*)&Wsm[k * C_OUT + c0];  // float4 as 2 packed pairs
#pragma unroll
        for (int i = 0; i < 8; ++i) {
            float xv = Xsm[(r0 + i) * F + k];
            u64 xp;
            asm("mov.b64 %0, {%1, %1};" : "=l"(xp) : "f"(xv));
            asm("fma.rn.f32x2 %0, %1, %2, %0;" : "+l"(acc01[i]) : "l"(xp), "l"(wp.x));
            asm("fma.rn.f32x2 %0, %1, %2, %0;" : "+l"(acc23[i]) : "l"(xp), "l"(wp.y));
        }
    }

#pragma unroll
    for (int i = 0; i < 8; ++i) {
        int r = base + r0 + i;
        if (r < n) {
            float dv = g_dinv[r];
            float a0, a1, a2, a3;
            asm("mov.b64 {%0, %1}, %2;" : "=f"(a0), "=f"(a1) : "l"(acc01[i]));
            asm("mov.b64 {%0, %1}, %2;" : "=f"(a2), "=f"(a3) : "l"(acc23[i]));
            float4 v;
            v.x = dv * a0;
            v.y = dv * a1;
            v.z = dv * a2;
            v.w = dv * a3;
            *(float4*)&g_xws[(size_t)r * C_OUT + c0] = v;
        }
    }
}

// ==================== gather + epilogue: out = dinv*(self + sum nbrs) + bfc2 ====================
// 16 threads per node, each owns one float4 column slot
__global__ void k_gather(float* __restrict__ out, int n) {
    int gt = blockIdx.x * blockDim.x + threadIdx.x;
    int r = gt >> 4;
    if (r >= n) return;
    int l4 = (gt & 15) * 4;

    int p0 = __ldg(&g_ptr[r]);
    int p1 = __ldg(&g_ptr[r + 1]);

    float4 acc = *(const float4*)&g_xws[(size_t)r * C_OUT + l4];  // self-loop

    int j = p0;
    int nxt = (j < p1) ? __ldg(&g_csr[j]) : 0;
    while (j < p1) {
        int idx = nxt;
        ++j;
        nxt = (j < p1) ? __ldg(&g_csr[j]) : 0;
        float4 v = *(const float4*)&g_xws[(size_t)idx * C_OUT + l4];
        acc.x += v.x; acc.y += v.y; acc.z += v.z; acc.w += v.w;
    }

    float dv = __ldg(&g_dinv[r]);
    float4 b = *(const float4*)&g_bfc2[l4];
    float4 o;
    o.x = fmaf(dv, acc.x, b.x);
    o.y = fmaf(dv, acc.y, b.y);
    o.z = fmaf(dv, acc.z, b.z);
    o.w = fmaf(dv, acc.w, b.w);
    *(float4*)&out[(size_t)r * C_OUT + l4] = o;
}

// ==================== launch ====================
extern "C" void kernel_launch(void* const* d_in, const int* in_sizes, int n_in,
                              void* d_out, int out_size) {
    const float* x    = (const float*)d_in[0];
    const int*   ei   = (const int*)d_in[1];
    const float* Wgcn = (const float*)d_in[2];
    const float* bgcn = (const float*)d_in[3];
    const float* Wfc  = (const float*)d_in[4];
    const float* bfc  = (const float*)d_in[5];
    float* out = (float*)d_out;

    int n = in_sizes[0] / F;       // 100000
    int e = in_sizes[1] / 2;       // 1600000

    static bool attr_set = false;
    if (!attr_set) {
        cudaFuncSetAttribute(k_xw, cudaFuncAttributeMaxDynamicSharedMemorySize,
                             (F * C_OUT + 128 * F) * 4);
        attr_set = true;
    }

    int nbs = (n + 1023) / 1024;                       // scan blocks (98)

    k_setup<<<1024 + 1 + nbs, 256>>>(Wgcn, Wfc, bgcn, bfc, n);

    int hthreads = (e + 3) / 4;
    k_hist<<<(hthreads + 255) / 256, 256>>>(ei + e, e);

    k_scan1<<<nbs, 256>>>(n);
    k_scan2<<<1, 256>>>(nbs);
    k_scan3<<<nbs, 256>>>(n, e);

    int gemm_blocks = (n + 127) / 128;
    k_xw<<<gemm_blocks, 256, (F * C_OUT + 128 * F) * 4>>>(x, n);

    int fthreads = (e + 1) / 2;
    k_fill<<<(fthreads + 255) / 256, 256>>>(ei, e);

    k_gather<<<(n * 16 + 255) / 256, 256>>>(out, n);
}